// round 2
// baseline (speedup 1.0000x reference)
#include <cuda_runtime.h>

#define GRID 128
#define NTHR 256
#define Bsz 64
#define Ssz 1024
#define Tsz 300
#define Hsz 512
#define Vsz 5000
#define KQn 256
#define KC  128
#define AP  133

// ---------------- device scratch (static, allocation-free) ----------------
__device__ float g_k[Bsz * Ssz * KQn];        // projected keys
__device__ float g_v[Bsz * Ssz * Hsz];        // projected values
__device__ float g_h1[2][Bsz * Hsz];
__device__ float g_c1[Bsz * Hsz];
__device__ float g_h2[2][Bsz * Hsz];
__device__ float g_c2[Bsz * Hsz];
__device__ float g_ctx[Bsz * Hsz];
__device__ float g_cdnp[4][Bsz * Hsz];        // cdn split-K partials
__device__ unsigned g_count;                   // barrier arrival counter
__device__ unsigned g_gen;                     // barrier generation

// ---------------- grid-wide barrier (generation counter) ----------------
__device__ __forceinline__ void gsync() {
    __syncthreads();
    if (threadIdx.x == 0) {
        __threadfence();
        volatile unsigned* genp = &g_gen;
        unsigned old = *genp;
        if (atomicAdd(&g_count, 1u) == gridDim.x - 1u) {
            atomicExch(&g_count, 0u);
            __threadfence();
            atomicAdd(&g_gen, 1u);
        } else {
            while (*genp == old) __nanosleep(64);
        }
        __threadfence();
    }
    __syncthreads();
}

__device__ __forceinline__ float sigf(float x) { return 1.f / (1.f + __expf(-x)); }

// ---------------- 64(M) x 16(N) GEMM chunk, K streamed in 128 slices -------
// out[b][c] = sum_k A[b][k] * B[n(c)][k], result staged to gout[64][17].
// MODE 0: kv-proj   A = A0 + b*512 (pre-offset enc rows), B width 512
// MODE 1: gates1    A = [emb[tok[b]] | ctx | h1old], B = [Wih1(1024) | Whh1(512)]
//                   col map n(c) = (c>>2)*512 + u0 + (c&3)
// MODE 2: gates2    A = [h1new | h2old], B = [Wih2(512) | Whh2(512)], same col map
// MODE 3: cdn       A = [h2new | ctx], B = Wcdn (width 1024), k range = quarter
// MODE 4: logits    A[b][k] = relu(bcdn[k] + sum_z cdnp[z][b][k]), B = emb (512)
template <int MODE>
__device__ __forceinline__ void gemm_chunk(
    int u0, int nbase, int Ntot, int kbeg, int kend,
    const float* __restrict__ A0, const float* __restrict__ A1,
    const float* __restrict__ A2,
    const float* __restrict__ B0, const float* __restrict__ B1,
    float (&As)[64][AP], float (&Bst)[KC][18], float (&gout)[64][17],
    const int* __restrict__ toks)
{
    const int tid = threadIdx.x;
    const int b2 = tid & 31, c2 = tid >> 5;
    float a00 = 0.f, a01 = 0.f, a10 = 0.f, a11 = 0.f;

    for (int k0 = kbeg; k0 < kend; k0 += KC) {
        // ---- A tile fill: 64 rows x 128 k, row-major, conflict-free STS ----
        {
            const int bb = tid & 63, kq = tid >> 6;   // kq 0..3
            if (MODE == 4) {
                const float* p = A0 + bb * 512 + k0;  // cdnp[0] row
#pragma unroll
                for (int i = 0; i < 8; i++) {
                    int kk = kq * 32 + i * 4;
                    float4 v0 = *(const float4*)(p + kk);
                    float4 v1 = *(const float4*)(p + 32768 + kk);
                    float4 v2 = *(const float4*)(p + 65536 + kk);
                    float4 v3 = *(const float4*)(p + 98304 + kk);
                    float4 vb = *(const float4*)(A1 + k0 + kk);
                    As[bb][kk + 0] = fmaxf(v0.x + v1.x + v2.x + v3.x + vb.x, 0.f);
                    As[bb][kk + 1] = fmaxf(v0.y + v1.y + v2.y + v3.y + vb.y, 0.f);
                    As[bb][kk + 2] = fmaxf(v0.z + v1.z + v2.z + v3.z + vb.z, 0.f);
                    As[bb][kk + 3] = fmaxf(v0.w + v1.w + v2.w + v3.w + vb.w, 0.f);
                }
            } else {
                const float* row;
                if (MODE == 0)      row = A0 + (long)bb * 512 + k0;
                else if (MODE == 1) row = (k0 < 512)
                        ? A0 + (long)toks[bb] * 512 + k0
                        : (k0 < 1024 ? A1 + bb * 512 + (k0 - 512)
                                     : A2 + bb * 512 + (k0 - 1024));
                else                row = (k0 < 512) ? A0 + bb * 512 + k0
                                                     : A1 + bb * 512 + (k0 - 512);
#pragma unroll
                for (int i = 0; i < 8; i++) {
                    int kk = kq * 32 + i * 4;
                    float4 v = *(const float4*)(row + kk);
                    As[bb][kk + 0] = v.x; As[bb][kk + 1] = v.y;
                    As[bb][kk + 2] = v.z; As[bb][kk + 3] = v.w;
                }
            }
        }
        // ---- B tile fill: 16 cols, transposed [k][c] for broadcast reads ----
        {
            const int c = tid >> 4, kq = tid & 15;
            int n = (MODE == 1 || MODE == 2) ? (((c >> 2) << 9) + u0 + (c & 3))
                                             : nbase + c;
            bool ok = n < Ntot;
            const float* row;
            if (MODE == 1)      row = (k0 < 1024) ? B0 + (long)n * 1024 + k0
                                                  : B1 + (long)n * 512 + (k0 - 1024);
            else if (MODE == 2) row = (k0 < 512) ? B0 + (long)n * 512 + k0
                                                 : B1 + (long)n * 512 + (k0 - 512);
            else if (MODE == 3) row = B0 + (long)n * 1024 + k0;
            else                row = B0 + (long)n * 512 + k0;
#pragma unroll
            for (int i = 0; i < 2; i++) {
                int kk = kq * 8 + i * 4;
                float4 v = ok ? *(const float4*)(row + kk)
                              : make_float4(0.f, 0.f, 0.f, 0.f);
                Bst[kk + 0][c] = v.x; Bst[kk + 1][c] = v.y;
                Bst[kk + 2][c] = v.z; Bst[kk + 3][c] = v.w;
            }
        }
        __syncthreads();
#pragma unroll 8
        for (int kk = 0; kk < KC; kk++) {
            float av0 = As[2 * b2][kk];
            float av1 = As[2 * b2 + 1][kk];
            float2 bv = *(const float2*)&Bst[kk][2 * c2];
            a00 += av0 * bv.x; a01 += av0 * bv.y;
            a10 += av1 * bv.x; a11 += av1 * bv.y;
        }
        __syncthreads();
    }
    gout[2 * b2][2 * c2]     = a00; gout[2 * b2][2 * c2 + 1]     = a01;
    gout[2 * b2 + 1][2 * c2] = a10; gout[2 * b2 + 1][2 * c2 + 1] = a11;
    __syncthreads();
}

// ---------------- the persistent mega-kernel ----------------
__global__ void __launch_bounds__(NTHR, 1)
mega(const float* __restrict__ enc, const int* __restrict__ y,
     const float* __restrict__ emb,
     const float* __restrict__ Wq, const float* __restrict__ bq,
     const float* __restrict__ Wk, const float* __restrict__ bk,
     const float* __restrict__ Wv, const float* __restrict__ bv,
     const float* __restrict__ Wih1, const float* __restrict__ bih1,
     const float* __restrict__ Whh1, const float* __restrict__ bhh1,
     const float* __restrict__ Wih2, const float* __restrict__ bih2,
     const float* __restrict__ Whh2, const float* __restrict__ bhh2,
     const float* __restrict__ Wcdn, const float* __restrict__ bcdn,
     const float* __restrict__ bcls, float* __restrict__ out)
{
    __shared__ __align__(16) float As[64][AP];
    __shared__ __align__(16) float Bst[KC][18];
    __shared__ __align__(16) float gout[64][17];
    __shared__ int toks[64];

    const int tid = threadIdx.x;
    const int bx = blockIdx.x;

    // ---- phase 0: zero recurrent state + kv projection ----
    if (bx < 5) {
        float* z = bx == 0 ? g_h1[0] : bx == 1 ? g_c1 : bx == 2 ? g_h2[0]
                 : bx == 3 ? g_c2 : g_ctx;
        for (int i = tid; i < Bsz * Hsz; i += NTHR) z[i] = 0.f;
    }
    for (int cid = bx; cid < 16384 + 32768; cid += GRID) {
        if (cid < 16384) {                              // k-proj chunk
            int rt = cid >> 4, nb = (cid & 15) * 16;
            gemm_chunk<0>(0, nb, 1 << 30, 0, 512, enc + (long)rt * 64 * 512,
                          nullptr, nullptr, Wk, nullptr, As, Bst, gout, toks);
            float* dst = g_k + (long)rt * 64 * KQn;
            for (int e = tid; e < 1024; e += NTHR) {
                int b = e >> 4, c = e & 15;
                dst[(long)b * KQn + nb + c] = gout[b][c] + bk[nb + c];
            }
            __syncthreads();
        } else {                                        // v-proj chunk
            int vid = cid - 16384;
            int rt = vid >> 5, nb = (vid & 31) * 16;
            gemm_chunk<0>(0, nb, 1 << 30, 0, 512, enc + (long)rt * 64 * 512,
                          nullptr, nullptr, Wv, nullptr, As, Bst, gout, toks);
            float* dst = g_v + (long)rt * 64 * Hsz;
            for (int e = tid; e < 1024; e += NTHR) {
                int b = e >> 4, c = e & 15;
                dst[(long)b * Hsz + nb + c] = gout[b][c] + bv[nb + c];
            }
            __syncthreads();
        }
    }
    gsync();

    // ---- decoder time loop ----
    for (int t = 0; t < Tsz; t++) {
        const float* h1o = g_h1[t & 1];
        float*       h1n = g_h1[(t + 1) & 1];
        const float* h2o = g_h2[t & 1];
        float*       h2n = g_h2[(t + 1) & 1];

        // Phase 1: LSTM1 gates GEMM + fused cell (block owns units 4*bx..4*bx+3)
        {
            if (tid < 64) toks[tid] = (t == 0) ? 0 : y[tid * Tsz + (t - 1)];
            __syncthreads();
            int u0 = bx * 4;
            gemm_chunk<1>(u0, 0, 1 << 30, 0, 1536, emb, g_ctx, h1o,
                          Wih1, Whh1, As, Bst, gout, toks);
            int b = tid >> 2, du = tid & 3, u = u0 + du;
            float gi = gout[b][du]      + bih1[u]          + bhh1[u];
            float gf = gout[b][4 + du]  + bih1[512 + u]    + bhh1[512 + u];
            float gg = gout[b][8 + du]  + bih1[1024 + u]   + bhh1[1024 + u];
            float go = gout[b][12 + du] + bih1[1536 + u]   + bhh1[1536 + u];
            float cold = g_c1[b * Hsz + u];
            float cn = sigf(gf) * cold + sigf(gi) * tanhf(gg);
            g_c1[b * Hsz + u] = cn;
            h1n[b * Hsz + u] = sigf(go) * tanhf(cn);
            gsync();
        }

        // Phase 2: LSTM2 gates GEMM + fused cell
        {
            int u0 = bx * 4;
            gemm_chunk<2>(u0, 0, 1 << 30, 0, 1024, h1n, h2o, nullptr,
                          Wih2, Whh2, As, Bst, gout, toks);
            int b = tid >> 2, du = tid & 3, u = u0 + du;
            float gi = gout[b][du]      + bih2[u]          + bhh2[u];
            float gf = gout[b][4 + du]  + bih2[512 + u]    + bhh2[512 + u];
            float gg = gout[b][8 + du]  + bih2[1024 + u]   + bhh2[1024 + u];
            float go = gout[b][12 + du] + bih2[1536 + u]   + bhh2[1536 + u];
            float cold = g_c2[b * Hsz + u];
            float cn = sigf(gf) * cold + sigf(gi) * tanhf(gg);
            g_c2[b * Hsz + u] = cn;
            h2n[b * Hsz + u] = sigf(go) * tanhf(cn);
            gsync();
        }

        // Phase 3: fused attention, one block per batch element
        if (bx < Bsz) {
            float* h2s = &As[0][0];
            float* qs  = h2s + 512;
            float* sc  = qs + 256;
            float* red = sc + 1024;
            int b = bx, lane = tid & 31, w = tid >> 5;

            h2s[tid]       = h2n[b * 512 + tid];
            h2s[tid + 256] = h2n[b * 512 + 256 + tid];
            __syncthreads();

            const float4* h24 = (const float4*)h2s;
            for (int jj = 0; jj < 32; jj++) {
                int j = (w << 5) + jj;
                const float4* wr = (const float4*)(Wq + (long)j * 512);
                float s = 0.f;
#pragma unroll
                for (int it = 0; it < 4; it++) {
                    float4 hv = h24[it * 32 + lane];
                    float4 wv = wr[it * 32 + lane];
                    s += hv.x * wv.x + hv.y * wv.y + hv.z * wv.z + hv.w * wv.w;
                }
#pragma unroll
                for (int o = 16; o; o >>= 1) s += __shfl_xor_sync(0xffffffffu, s, o);
                if (lane == 0) qs[j] = (s + bq[j]) * 0.0625f;
            }
            __syncthreads();

            const float4* q4 = (const float4*)qs;
            float4 qr0 = q4[lane], qr1 = q4[32 + lane];
#pragma unroll 2
            for (int i = 0; i < 128; i++) {
                int sidx = (i << 3) + w;
                const float4* kr = (const float4*)(g_k + ((long)b * 1024 + sidx) * 256);
                float4 k0 = kr[lane], k1 = kr[32 + lane];
                float acc = qr0.x * k0.x + qr0.y * k0.y + qr0.z * k0.z + qr0.w * k0.w
                          + qr1.x * k1.x + qr1.y * k1.y + qr1.z * k1.z + qr1.w * k1.w;
#pragma unroll
                for (int o = 16; o; o >>= 1) acc += __shfl_xor_sync(0xffffffffu, acc, o);
                if (lane == 0) sc[sidx] = acc;
            }
            __syncthreads();

            float mx = -1e30f;
#pragma unroll
            for (int i = 0; i < 4; i++) mx = fmaxf(mx, sc[tid + i * 256]);
#pragma unroll
            for (int o = 16; o; o >>= 1) mx = fmaxf(mx, __shfl_xor_sync(0xffffffffu, mx, o));
            if (lane == 0) red[w] = mx;
            __syncthreads();
            mx = red[0];
#pragma unroll
            for (int i = 1; i < 8; i++) mx = fmaxf(mx, red[i]);
            __syncthreads();

            float ls = 0.f;
#pragma unroll
            for (int i = 0; i < 4; i++) {
                float e = __expf(sc[tid + i * 256] - mx);
                sc[tid + i * 256] = e;
                ls += e;
            }
#pragma unroll
            for (int o = 16; o; o >>= 1) ls += __shfl_xor_sync(0xffffffffu, ls, o);
            if (lane == 0) red[w] = ls;
            __syncthreads();
            float tot = red[0] + red[1] + red[2] + red[3]
                      + red[4] + red[5] + red[6] + red[7];
            float inv = 1.f / tot;

            float2 acc2 = make_float2(0.f, 0.f);
            const float2* vb = (const float2*)(g_v + (long)b * 1024 * 512);
#pragma unroll 4
            for (int s2 = 0; s2 < 1024; s2++) {
                float wsc = sc[s2];
                float2 vv = vb[(long)s2 * 256 + tid];
                acc2.x += wsc * vv.x;
                acc2.y += wsc * vv.y;
            }
            g_ctx[b * 512 + 2 * tid]     = acc2.x * inv;
            g_ctx[b * 512 + 2 * tid + 1] = acc2.y * inv;
        }
        gsync();

        // Phase 4: cdn partial GEMM (32 col-chunks x 4-way split-K)
        {
            int nb = (bx >> 2) * 16;
            int kq = bx & 3;
            gemm_chunk<3>(0, nb, 1 << 30, kq * 256, kq * 256 + 256, h2n, g_ctx,
                          nullptr, Wcdn, nullptr, As, Bst, gout, toks);
            float* dst = g_cdnp[kq];
            for (int e = tid; e < 1024; e += NTHR) {
                int b = e >> 4, c = e & 15;
                dst[b * Hsz + nb + c] = gout[b][c];
            }
            gsync();
        }

        // Phase 5: logits GEMM (cdn finish fused into A load), 313 chunks
        {
            for (int ci = bx; ci < 313; ci += GRID) {
                int nb = ci * 16;
                gemm_chunk<4>(0, nb, Vsz, 0, 512, g_cdnp[0], bcdn, nullptr,
                              emb, nullptr, As, Bst, gout, toks);
                for (int e = tid; e < 1024; e += NTHR) {
                    int b = e >> 4, c = e & 15;
                    int n = nb + c;
                    if (n < Vsz)
                        out[((long)b * Tsz + t) * Vsz + n] = gout[b][c] + bcls[n];
                }
                __syncthreads();
            }
            gsync();
        }
    }
}

// ---------------- host launch: ONE kernel, ONE graph node ----------------
extern "C" void kernel_launch(void* const* d_in, const int* in_sizes, int n_in,
                              void* d_out, int out_size) {
    mega<<<GRID, NTHR>>>(
        (const float*)d_in[0],  (const int*)d_in[1],   (const float*)d_in[2],
        (const float*)d_in[3],  (const float*)d_in[4],
        (const float*)d_in[5],  (const float*)d_in[6],
        (const float*)d_in[7],  (const float*)d_in[8],
        (const float*)d_in[9],  (const float*)d_in[10],
        (const float*)d_in[11], (const float*)d_in[12],
        (const float*)d_in[13], (const float*)d_in[14],
        (const float*)d_in[15], (const float*)d_in[16],
        (const float*)d_in[17], (const float*)d_in[18],
        (const float*)d_in[19], (float*)d_out);
}

// round 3
// speedup vs baseline: 1.0235x; 1.0235x over previous
#include <cuda_runtime.h>

#define GRID 128
#define NTHR 256
#define Bsz 64
#define Ssz 1024
#define Tsz 300
#define Hsz 512
#define Vsz 5000
#define KQn 256
#define KC  128
#define AP  133

// ---------------- device scratch (static, allocation-free) ----------------
__device__ float g_k[Bsz * Ssz * KQn];        // projected keys
__device__ float g_v[Bsz * Ssz * Hsz];        // projected values
__device__ float g_h1[2][Bsz * Hsz];
__device__ float g_c1[Bsz * Hsz];
__device__ float g_h2[2][Bsz * Hsz];
__device__ float g_c2[Bsz * Hsz];
__device__ float g_ctx[Bsz * Hsz];
__device__ float g_cdnp[4][Bsz * Hsz];        // cdn split-K partials
__device__ unsigned g_count;                   // barrier arrival counter
__device__ unsigned g_gen;                     // barrier generation

// ---------------- grid-wide barrier (generation counter) ----------------
__device__ __forceinline__ void gsync() {
    __syncthreads();
    if (threadIdx.x == 0) {
        __threadfence();
        volatile unsigned* genp = &g_gen;
        unsigned old = *genp;
        if (atomicAdd(&g_count, 1u) == gridDim.x - 1u) {
            atomicExch(&g_count, 0u);
            __threadfence();
            atomicAdd(&g_gen, 1u);
        } else {
            while (*genp == old) __nanosleep(64);
        }
        __threadfence();
    }
    __syncthreads();
}

__device__ __forceinline__ float sigf(float x) { return 1.f / (1.f + __expf(-x)); }

// ---------------- 64(M) x 16(N) GEMM chunk, K streamed in 128 slices -------
// out[b][c] = sum_k A[b][k] * B[n(c)][k], result staged to gout[64][17].
// MODE 0: kv-proj   A = A0 + b*512 (pre-offset enc rows), B width 512
// MODE 1: gates1    A = [emb[tok[b]] | ctx | h1old], B = [Wih1(1024) | Whh1(512)]
//                   col map n(c) = (c>>2)*512 + u0 + (c&3)
// MODE 2: gates2    A = [h1new | h2old], B = [Wih2(512) | Whh2(512)], same col map
// MODE 3: cdn       A = [h2new | ctx], B = Wcdn (width 1024), k range = quarter
// MODE 4: logits    A[b][k] = relu(bcdn[k] + sum_z cdnp[z][b][k]), B = emb (512)
template <int MODE>
__device__ __forceinline__ void gemm_chunk(
    int u0, int nbase, int Ntot, int kbeg, int kend,
    const float* __restrict__ A0, const float* __restrict__ A1,
    const float* __restrict__ A2,
    const float* __restrict__ B0, const float* __restrict__ B1,
    float (&As)[64][AP], float (&Bst)[KC][18], float (&gout)[64][17],
    const int* __restrict__ toks)
{
    const int tid = threadIdx.x;
    const int b2 = tid & 31, c2 = tid >> 5;
    float a00 = 0.f, a01 = 0.f, a10 = 0.f, a11 = 0.f;

    for (int k0 = kbeg; k0 < kend; k0 += KC) {
        // ---- A tile fill: 64 rows x 128 k, row-major, conflict-free STS ----
        {
            const int bb = tid & 63, kq = tid >> 6;   // kq 0..3
            if (MODE == 4) {
                const float* p = A0 + bb * 512 + k0;  // cdnp[0] row
#pragma unroll
                for (int i = 0; i < 8; i++) {
                    int kk = kq * 32 + i * 4;
                    float4 v0 = *(const float4*)(p + kk);
                    float4 v1 = *(const float4*)(p + 32768 + kk);
                    float4 v2 = *(const float4*)(p + 65536 + kk);
                    float4 v3 = *(const float4*)(p + 98304 + kk);
                    float4 vb = *(const float4*)(A1 + k0 + kk);
                    As[bb][kk + 0] = fmaxf(v0.x + v1.x + v2.x + v3.x + vb.x, 0.f);
                    As[bb][kk + 1] = fmaxf(v0.y + v1.y + v2.y + v3.y + vb.y, 0.f);
                    As[bb][kk + 2] = fmaxf(v0.z + v1.z + v2.z + v3.z + vb.z, 0.f);
                    As[bb][kk + 3] = fmaxf(v0.w + v1.w + v2.w + v3.w + vb.w, 0.f);
                }
            } else {
                const float* row;
                if (MODE == 0)      row = A0 + (long)bb * 512 + k0;
                else if (MODE == 1) row = (k0 < 512)
                        ? A0 + (long)toks[bb] * 512 + k0
                        : (k0 < 1024 ? A1 + bb * 512 + (k0 - 512)
                                     : A2 + bb * 512 + (k0 - 1024));
                else                row = (k0 < 512) ? A0 + bb * 512 + k0
                                                     : A1 + bb * 512 + (k0 - 512);
#pragma unroll
                for (int i = 0; i < 8; i++) {
                    int kk = kq * 32 + i * 4;
                    float4 v = *(const float4*)(row + kk);
                    As[bb][kk + 0] = v.x; As[bb][kk + 1] = v.y;
                    As[bb][kk + 2] = v.z; As[bb][kk + 3] = v.w;
                }
            }
        }
        // ---- B tile fill: 16 cols, transposed [k][c] for broadcast reads ----
        {
            const int c = tid >> 4, kq = tid & 15;
            int n = (MODE == 1 || MODE == 2) ? (((c >> 2) << 9) + u0 + (c & 3))
                                             : nbase + c;
            bool ok = n < Ntot;
            const float* row;
            if (MODE == 1)      row = (k0 < 1024) ? B0 + (long)n * 1024 + k0
                                                  : B1 + (long)n * 512 + (k0 - 1024);
            else if (MODE == 2) row = (k0 < 512) ? B0 + (long)n * 512 + k0
                                                 : B1 + (long)n * 512 + (k0 - 512);
            else if (MODE == 3) row = B0 + (long)n * 1024 + k0;
            else                row = B0 + (long)n * 512 + k0;
#pragma unroll
            for (int i = 0; i < 2; i++) {
                int kk = kq * 8 + i * 4;
                float4 v = ok ? *(const float4*)(row + kk)
                              : make_float4(0.f, 0.f, 0.f, 0.f);
                Bst[kk + 0][c] = v.x; Bst[kk + 1][c] = v.y;
                Bst[kk + 2][c] = v.z; Bst[kk + 3][c] = v.w;
            }
        }
        __syncthreads();
#pragma unroll 8
        for (int kk = 0; kk < KC; kk++) {
            float av0 = As[2 * b2][kk];
            float av1 = As[2 * b2 + 1][kk];
            float2 bv = *(const float2*)&Bst[kk][2 * c2];
            a00 += av0 * bv.x; a01 += av0 * bv.y;
            a10 += av1 * bv.x; a11 += av1 * bv.y;
        }
        __syncthreads();
    }
    gout[2 * b2][2 * c2]     = a00; gout[2 * b2][2 * c2 + 1]     = a01;
    gout[2 * b2 + 1][2 * c2] = a10; gout[2 * b2 + 1][2 * c2 + 1] = a11;
    __syncthreads();
}

// ---------------- the persistent mega-kernel ----------------
__global__ void __launch_bounds__(NTHR, 1)
mega(const float* __restrict__ enc, const int* __restrict__ y,
     const float* __restrict__ emb,
     const float* __restrict__ Wq, const float* __restrict__ bq,
     const float* __restrict__ Wk, const float* __restrict__ bk,
     const float* __restrict__ Wv, const float* __restrict__ bv,
     const float* __restrict__ Wih1, const float* __restrict__ bih1,
     const float* __restrict__ Whh1, const float* __restrict__ bhh1,
     const float* __restrict__ Wih2, const float* __restrict__ bih2,
     const float* __restrict__ Whh2, const float* __restrict__ bhh2,
     const float* __restrict__ Wcdn, const float* __restrict__ bcdn,
     const float* __restrict__ bcls, float* __restrict__ out)
{
    __shared__ __align__(16) float As[64][AP];
    __shared__ __align__(16) float Bst[KC][18];
    __shared__ __align__(16) float gout[64][17];
    __shared__ int toks[64];

    const int tid = threadIdx.x;
    const int bx = blockIdx.x;

    // ---- phase 0: zero recurrent state + kv projection ----
    if (bx < 5) {
        float* z = bx == 0 ? g_h1[0] : bx == 1 ? g_c1 : bx == 2 ? g_h2[0]
                 : bx == 3 ? g_c2 : g_ctx;
        for (int i = tid; i < Bsz * Hsz; i += NTHR) z[i] = 0.f;
    }
    for (int cid = bx; cid < 16384 + 32768; cid += GRID) {
        if (cid < 16384) {                              // k-proj chunk
            int rt = cid >> 4, nb = (cid & 15) * 16;
            gemm_chunk<0>(0, nb, 1 << 30, 0, 512, enc + (long)rt * 64 * 512,
                          nullptr, nullptr, Wk, nullptr, As, Bst, gout, toks);
            float* dst = g_k + (long)rt * 64 * KQn;
            for (int e = tid; e < 1024; e += NTHR) {
                int b = e >> 4, c = e & 15;
                dst[(long)b * KQn + nb + c] = gout[b][c] + bk[nb + c];
            }
            __syncthreads();
        } else {                                        // v-proj chunk
            int vid = cid - 16384;
            int rt = vid >> 5, nb = (vid & 31) * 16;
            gemm_chunk<0>(0, nb, 1 << 30, 0, 512, enc + (long)rt * 64 * 512,
                          nullptr, nullptr, Wv, nullptr, As, Bst, gout, toks);
            float* dst = g_v + (long)rt * 64 * Hsz;
            for (int e = tid; e < 1024; e += NTHR) {
                int b = e >> 4, c = e & 15;
                dst[(long)b * Hsz + nb + c] = gout[b][c] + bv[nb + c];
            }
            __syncthreads();
        }
    }
    gsync();

    // ---- decoder time loop ----
    for (int t = 0; t < Tsz; t++) {
        const float* h1o = g_h1[t & 1];
        float*       h1n = g_h1[(t + 1) & 1];
        const float* h2o = g_h2[t & 1];
        float*       h2n = g_h2[(t + 1) & 1];

        // Phase 1: LSTM1 gates GEMM + fused cell (block owns units 4*bx..4*bx+3)
        {
            if (tid < 64) toks[tid] = (t == 0) ? 0 : y[tid * Tsz + (t - 1)];
            __syncthreads();
            int u0 = bx * 4;
            gemm_chunk<1>(u0, 0, 1 << 30, 0, 1536, emb, g_ctx, h1o,
                          Wih1, Whh1, As, Bst, gout, toks);
            int b = tid >> 2, du = tid & 3, u = u0 + du;
            float gi = gout[b][du]      + bih1[u]          + bhh1[u];
            float gf = gout[b][4 + du]  + bih1[512 + u]    + bhh1[512 + u];
            float gg = gout[b][8 + du]  + bih1[1024 + u]   + bhh1[1024 + u];
            float go = gout[b][12 + du] + bih1[1536 + u]   + bhh1[1536 + u];
            float cold = g_c1[b * Hsz + u];
            float cn = sigf(gf) * cold + sigf(gi) * tanhf(gg);
            g_c1[b * Hsz + u] = cn;
            h1n[b * Hsz + u] = sigf(go) * tanhf(cn);
            gsync();
        }

        // Phase 2: LSTM2 gates GEMM + fused cell
        {
            int u0 = bx * 4;
            gemm_chunk<2>(u0, 0, 1 << 30, 0, 1024, h1n, h2o, nullptr,
                          Wih2, Whh2, As, Bst, gout, toks);
            int b = tid >> 2, du = tid & 3, u = u0 + du;
            float gi = gout[b][du]      + bih2[u]          + bhh2[u];
            float gf = gout[b][4 + du]  + bih2[512 + u]    + bhh2[512 + u];
            float gg = gout[b][8 + du]  + bih2[1024 + u]   + bhh2[1024 + u];
            float go = gout[b][12 + du] + bih2[1536 + u]   + bhh2[1536 + u];
            float cold = g_c2[b * Hsz + u];
            float cn = sigf(gf) * cold + sigf(gi) * tanhf(gg);
            g_c2[b * Hsz + u] = cn;
            h2n[b * Hsz + u] = sigf(go) * tanhf(cn);
            gsync();
        }

        // Phase 3: fused attention, one block per batch element
        if (bx < Bsz) {
            float* h2s = &As[0][0];
            float* qs  = h2s + 512;
            float* sc  = qs + 256;
            float* red = sc + 1024;
            int b = bx, lane = tid & 31, w = tid >> 5;

            h2s[tid]       = h2n[b * 512 + tid];
            h2s[tid + 256] = h2n[b * 512 + 256 + tid];
            __syncthreads();

            const float4* h24 = (const float4*)h2s;
            for (int jj = 0; jj < 32; jj++) {
                int j = (w << 5) + jj;
                const float4* wr = (const float4*)(Wq + (long)j * 512);
                float s = 0.f;
#pragma unroll
                for (int it = 0; it < 4; it++) {
                    float4 hv = h24[it * 32 + lane];
                    float4 wv = wr[it * 32 + lane];
                    s += hv.x * wv.x + hv.y * wv.y + hv.z * wv.z + hv.w * wv.w;
                }
#pragma unroll
                for (int o = 16; o; o >>= 1) s += __shfl_xor_sync(0xffffffffu, s, o);
                if (lane == 0) qs[j] = (s + bq[j]) * 0.0625f;
            }
            __syncthreads();

            const float4* q4 = (const float4*)qs;
            float4 qr0 = q4[lane], qr1 = q4[32 + lane];
#pragma unroll 2
            for (int i = 0; i < 128; i++) {
                int sidx = (i << 3) + w;
                const float4* kr = (const float4*)(g_k + ((long)b * 1024 + sidx) * 256);
                float4 k0 = kr[lane], k1 = kr[32 + lane];
                float acc = qr0.x * k0.x + qr0.y * k0.y + qr0.z * k0.z + qr0.w * k0.w
                          + qr1.x * k1.x + qr1.y * k1.y + qr1.z * k1.z + qr1.w * k1.w;
#pragma unroll
                for (int o = 16; o; o >>= 1) acc += __shfl_xor_sync(0xffffffffu, acc, o);
                if (lane == 0) sc[sidx] = acc;
            }
            __syncthreads();

            float mx = -1e30f;
#pragma unroll
            for (int i = 0; i < 4; i++) mx = fmaxf(mx, sc[tid + i * 256]);
#pragma unroll
            for (int o = 16; o; o >>= 1) mx = fmaxf(mx, __shfl_xor_sync(0xffffffffu, mx, o));
            if (lane == 0) red[w] = mx;
            __syncthreads();
            mx = red[0];
#pragma unroll
            for (int i = 1; i < 8; i++) mx = fmaxf(mx, red[i]);
            __syncthreads();

            float ls = 0.f;
#pragma unroll
            for (int i = 0; i < 4; i++) {
                float e = __expf(sc[tid + i * 256] - mx);
                sc[tid + i * 256] = e;
                ls += e;
            }
#pragma unroll
            for (int o = 16; o; o >>= 1) ls += __shfl_xor_sync(0xffffffffu, ls, o);
            if (lane == 0) red[w] = ls;
            __syncthreads();
            float tot = red[0] + red[1] + red[2] + red[3]
                      + red[4] + red[5] + red[6] + red[7];
            float inv = 1.f / tot;

            float2 acc2 = make_float2(0.f, 0.f);
            const float2* vb = (const float2*)(g_v + (long)b * 1024 * 512);
#pragma unroll 4
            for (int s2 = 0; s2 < 1024; s2++) {
                float wsc = sc[s2];
                float2 vv = vb[(long)s2 * 256 + tid];
                acc2.x += wsc * vv.x;
                acc2.y += wsc * vv.y;
            }
            g_ctx[b * 512 + 2 * tid]     = acc2.x * inv;
            g_ctx[b * 512 + 2 * tid + 1] = acc2.y * inv;
        }
        gsync();

        // Phase 4: cdn partial GEMM (32 col-chunks x 4-way split-K)
        {
            int nb = (bx >> 2) * 16;
            int kq = bx & 3;
            gemm_chunk<3>(0, nb, 1 << 30, kq * 256, kq * 256 + 256, h2n, g_ctx,
                          nullptr, Wcdn, nullptr, As, Bst, gout, toks);
            float* dst = g_cdnp[kq];
            for (int e = tid; e < 1024; e += NTHR) {
                int b = e >> 4, c = e & 15;
                dst[b * Hsz + nb + c] = gout[b][c];
            }
            gsync();
        }

        // Phase 5: logits GEMM (cdn finish fused into A load), 313 chunks
        {
            for (int ci = bx; ci < 313; ci += GRID) {
                int nb = ci * 16;
                gemm_chunk<4>(0, nb, Vsz, 0, 512, g_cdnp[0], bcdn, nullptr,
                              emb, nullptr, As, Bst, gout, toks);
                for (int e = tid; e < 1024; e += NTHR) {
                    int b = e >> 4, c = e & 15;
                    int n = nb + c;
                    if (n < Vsz)
                        out[((long)b * Tsz + t) * Vsz + n] = gout[b][c] + bcls[n];
                }
                __syncthreads();
            }
            gsync();
        }
    }
}

// ---------------- host launch: ONE kernel, ONE graph node ----------------
extern "C" void kernel_launch(void* const* d_in, const int* in_sizes, int n_in,
                              void* d_out, int out_size) {
    mega<<<GRID, NTHR>>>(
        (const float*)d_in[0],  (const int*)d_in[1],   (const float*)d_in[2],
        (const float*)d_in[3],  (const float*)d_in[4],
        (const float*)d_in[5],  (const float*)d_in[6],
        (const float*)d_in[7],  (const float*)d_in[8],
        (const float*)d_in[9],  (const float*)d_in[10],
        (const float*)d_in[11], (const float*)d_in[12],
        (const float*)d_in[13], (const float*)d_in[14],
        (const float*)d_in[15], (const float*)d_in[16],
        (const float*)d_in[17], (const float*)d_in[18],
        (const float*)d_in[19], (float*)d_out);
}